// round 16
// baseline (speedup 1.0000x reference)
#include <cuda_runtime.h>
#include <cuda_fp16.h>
#include <math.h>

typedef unsigned int u32;

// ---- problem constants ----
#define B_    64
#define CIN   16
#define H_    256
#define W_    256
#define COUT  64
#define OH    254
#define OW    254

// ---- implicit GEMM tiling: 256 pixels (16x16) x 64 co, K = 144 = 9 x 16 ----
// 8 warps, warp w owns pixel rows {2w, 2w+1}: two m16 tiles sharing B loads.
#define PT      16
#define KTOT    144
#define NCHUNK  9
#define THREADS 256
#define TPC     4            // tiles per CTA (along width)

// ---- smem layout (bytes) ----
#define OFF_BIASP  0                         // float2[32] bias pairs (256 B)
#define OFF_LUT    256                       // u32[72] packed u16 offset pairs (288 B)
#define OFF_HALO0  1024                      // fp32 [16ci][18r][20p] = 23040 B
#define HALO_BYTES 23040
#define OFF_HALO1  (OFF_HALO0 + HALO_BYTES)
#define OFF_BF     (OFF_HALO1 + HALO_BYTES)  // B fragments, 80 B/lane pitch = 23040 B
#define SMEM_BYTES (OFF_BF + 23040)          // 70144

// B fragments: u32[(c*32+lane)*20 + nb*2 + r]  (lane pitch 20 u32 = 80 B, 64 used)
__device__ u32 g_Bf[NCHUNK * 32 * 20];

// m16n8k16 row.col f32.f16.f16.f32
__device__ __forceinline__ void mma16816(float c[4], const u32 a[4], u32 b0, u32 b1) {
    asm volatile(
        "mma.sync.aligned.m16n8k16.row.col.f32.f16.f16.f32 "
        "{%0,%1,%2,%3}, {%4,%5,%6,%7}, {%8,%9}, {%0,%1,%2,%3};"
        : "+f"(c[0]), "+f"(c[1]), "+f"(c[2]), "+f"(c[3])
        : "r"(a[0]), "r"(a[1]), "r"(a[2]), "r"(a[3]), "r"(b0), "r"(b1));
}
__device__ __forceinline__ u32 pkhf2(float hi_f, float lo_f) {
    u32 r; asm("cvt.rn.f16x2.f32 %0, %1, %2;" : "=r"(r) : "f"(hi_f), "f"(lo_f)); return r;
}

// ============ weight prep: fp16 fragment-layout into g_Bf (padded pitch) ============
__global__ void wprep_kernel(const float* __restrict__ wg) {
    int idx = blockIdx.x * blockDim.x + threadIdx.x;      // (c, nb, lane)
    if (idx >= NCHUNK * 8 * 32) return;
    int lane = idx & 31;
    int nb   = (idx >> 5) & 7;
    int c    = idx >> 8;                                  // 0..8
    int n = nb * 8 + (lane >> 2);
    #pragma unroll
    for (int r = 0; r < 2; r++) {
        int kbase = c * 16 + r * 8 + 2 * (lane & 3);
        u32 pack = 0;
        #pragma unroll
        for (int e = 0; e < 2; e++) {
            int k = kbase + e;
            float v = 0.0f;
            if (k < KTOT) {
                int ci = k / 9, r9 = k % 9, kh = r9 / 3, kw = r9 % 3;
                v = wg[((n * CIN + ci) * 3 + kh) * 3 + kw];
            }
            pack |= (u32)__half_as_ushort(__float2half_rn(v)) << (e * 16);
        }
        g_Bf[(c * 32 + lane) * 20 + nb * 2 + r] = pack;
    }
}

// halo loader: [16ci][18r][20 pitch], zero-fill OOB
__device__ __forceinline__ void load_halo(float* halo, const float* xb,
                                          int oh0, int ow0, int tid) {
    #pragma unroll 1
    for (int i = tid; i < CIN * 18 * 18; i += THREADS) {
        int ci = i / 324; int rem = i - ci * 324;
        int r = rem / 18; int c = rem - r * 18;
        int gr = oh0 + r, gc = ow0 + c;
        float v = 0.0f;
        if (gr < H_ && gc < W_) v = xb[ci * (H_ * W_) + gr * W_ + gc];
        halo[(ci * 18 + r) * 20 + c] = v;
    }
}

// ============ main kernel ============
__global__ __launch_bounds__(THREADS, 2)
void conv_mma_kernel(const float* __restrict__ x,
                     const float* __restrict__ bias,
                     float* __restrict__ out)
{
    extern __shared__ __align__(16) unsigned char smem[];
    const int tid  = threadIdx.x;
    const int wid  = tid >> 5;
    const int lane = tid & 31;
    const int q    = lane & 3;
    const int b    = blockIdx.z;
    const int oh0  = blockIdx.y * PT;
    const int owg  = blockIdx.x * (PT * TPC);
    const float* xb = x + (size_t)b * (CIN * H_ * W_);

    // ---- one-time per CTA: B fragments, bias pairs, packed offset LUT, halo[0] ----
    {
        uint4*       d = (uint4*)(smem + OFF_BF);
        const uint4* s = (const uint4*)g_Bf;
        #pragma unroll 1
        for (int i = tid; i < 23040 / 16; i += THREADS) d[i] = s[i];
    }
    if (tid < 32) {
        int nb = tid >> 2, j = tid & 3;
        ((float2*)(smem + OFF_BIASP))[tid] =
            make_float2(bias[nb * 8 + 2 * j], bias[nb * 8 + 2 * j + 1]);
    }
    if (tid < 72) {   // packed offsets (pitch-20, 18 rows/ci): k0 = c*16 + 2q + 8*half
        int half = tid & 1, qq = (tid >> 1) & 3, c = tid >> 3;
        int k0 = c * 16 + 2 * qq + 8 * half;
        u32 o0, o1;
        {
            int k = k0, ci = k / 9, r9 = k % 9, kh = r9 / 3, kw = r9 % 3;
            o0 = (u32)(((ci * 18 + kh) * 20 + kw) * 4);
        }
        {
            int k = k0 + 1, ci = k / 9, r9 = k % 9, kh = r9 / 3, kw = r9 % 3;
            o1 = (u32)(((ci * 18 + kh) * 20 + kw) * 4);
        }
        ((u32*)(smem + OFF_LUT))[tid] = o0 | (o1 << 16);
    }
    load_halo((float*)(smem + OFF_HALO0), xb, oh0, owg, tid);
    __syncthreads();

    // hoist packed offsets into registers (loop-invariant)
    u32 lp[NCHUNK * 2];
    {
        const u32* lut = (const u32*)(smem + OFF_LUT);
        #pragma unroll
        for (int c = 0; c < NCHUNK; c++) {
            lp[c * 2 + 0] = lut[c * 8 + q * 2 + 0];
            lp[c * 2 + 1] = lut[c * 8 + q * 2 + 1];
        }
    }
    const unsigned char* bfp = smem + OFF_BF + lane * 80;
    // warp w: pixel rows {2w, 2w+1}; within a row, m = pixel col (lane>>2, +8)
    const u32 offm0 = (u32)(((wid * 2) * 20 + (lane >> 2)) * 4);

    #pragma unroll 1
    for (int t = 0; t < TPC; t++) {
        const int ow0 = owg + t * PT;
        const unsigned char* hbase = smem + ((t & 1) ? OFF_HALO1 : OFF_HALO0);
        const unsigned char* hA0 = hbase + offm0;        // row 2w, col lane>>2
        const unsigned char* hB0 = hA0 + 32;             // +8 pixel cols
        const unsigned char* hA1 = hA0 + 80;             // row 2w+1
        const unsigned char* hB1 = hA1 + 32;

        float acc0[8][4], acc1[8][4];
        #pragma unroll
        for (int nb = 0; nb < 8; nb++)
            #pragma unroll
            for (int r = 0; r < 4; r++) { acc0[nb][r] = 0.0f; acc1[nb][r] = 0.0f; }

        #pragma unroll
        for (int c = 0; c < NCHUNK; c++) {
            u32 pk0 = lp[c * 2 + 0];
            u32 pk1 = lp[c * 2 + 1];
            u32 oA = pk0 & 0xFFFFu, oB = pk0 >> 16;
            u32 oC = pk1 & 0xFFFFu, oD = pk1 >> 16;

            u32 a0[4], a1[4];
            {
                float v0 = *(const float*)(hA0 + oA);
                float v1 = *(const float*)(hA0 + oB);
                float v2 = *(const float*)(hA0 + oC);
                float v3 = *(const float*)(hA0 + oD);
                float w0 = *(const float*)(hB0 + oA);
                float w1 = *(const float*)(hB0 + oB);
                float w2 = *(const float*)(hB0 + oC);
                float w3 = *(const float*)(hB0 + oD);
                a0[0] = pkhf2(v1, v0); a0[1] = pkhf2(w1, w0);
                a0[2] = pkhf2(v3, v2); a0[3] = pkhf2(w3, w2);
            }
            {
                float v0 = *(const float*)(hA1 + oA);
                float v1 = *(const float*)(hA1 + oB);
                float v2 = *(const float*)(hA1 + oC);
                float v3 = *(const float*)(hA1 + oD);
                float w0 = *(const float*)(hB1 + oA);
                float w1 = *(const float*)(hB1 + oB);
                float w2 = *(const float*)(hB1 + oC);
                float w3 = *(const float*)(hB1 + oD);
                a1[0] = pkhf2(v1, v0); a1[1] = pkhf2(w1, w0);
                a1[2] = pkhf2(v3, v2); a1[3] = pkhf2(w3, w2);
            }

            const uint4* bq = (const uint4*)(bfp + c * 2560);
            uint4 w01 = bq[0];
            uint4 w23 = bq[1];
            uint4 w45 = bq[2];
            uint4 w67 = bq[3];
            mma16816(acc0[0], a0, w01.x, w01.y);
            mma16816(acc1[0], a1, w01.x, w01.y);
            mma16816(acc0[1], a0, w01.z, w01.w);
            mma16816(acc1[1], a1, w01.z, w01.w);
            mma16816(acc0[2], a0, w23.x, w23.y);
            mma16816(acc1[2], a1, w23.x, w23.y);
            mma16816(acc0[3], a0, w23.z, w23.w);
            mma16816(acc1[3], a1, w23.z, w23.w);
            mma16816(acc0[4], a0, w45.x, w45.y);
            mma16816(acc1[4], a1, w45.x, w45.y);
            mma16816(acc0[5], a0, w45.z, w45.w);
            mma16816(acc1[5], a1, w45.z, w45.w);
            mma16816(acc0[6], a0, w67.x, w67.y);
            mma16816(acc1[6], a1, w67.x, w67.y);
            mma16816(acc0[7], a0, w67.z, w67.w);
            mma16816(acc1[7], a1, w67.z, w67.w);
        }

        // ---- prefetch halo for tile t+1 (overlaps epilogue) ----
        if (t + 1 < TPC)
            load_halo((float*)(smem + ((t & 1) ? OFF_HALO0 : OFF_HALO1)),
                      xb, oh0, ow0 + PT, tid);

        // ---- epilogue: +bias, min over co, tanh^2, store ----
        {
            const float2* bp = (const float2*)(smem + OFF_BIASP);
            float mA0 = INFINITY, mB0 = INFINITY, mA1 = INFINITY, mB1 = INFINITY;
            #pragma unroll
            for (int nb = 0; nb < 8; nb++) {
                float2 bb = bp[nb * 4 + q];
                mA0 = fminf(mA0, fminf(acc0[nb][0] + bb.x, acc0[nb][1] + bb.y));
                mB0 = fminf(mB0, fminf(acc0[nb][2] + bb.x, acc0[nb][3] + bb.y));
                mA1 = fminf(mA1, fminf(acc1[nb][0] + bb.x, acc1[nb][1] + bb.y));
                mB1 = fminf(mB1, fminf(acc1[nb][2] + bb.x, acc1[nb][3] + bb.y));
            }
            mA0 = fminf(mA0, __shfl_xor_sync(0xFFFFFFFFu, mA0, 1));
            mA0 = fminf(mA0, __shfl_xor_sync(0xFFFFFFFFu, mA0, 2));
            mB0 = fminf(mB0, __shfl_xor_sync(0xFFFFFFFFu, mB0, 1));
            mB0 = fminf(mB0, __shfl_xor_sync(0xFFFFFFFFu, mB0, 2));
            mA1 = fminf(mA1, __shfl_xor_sync(0xFFFFFFFFu, mA1, 1));
            mA1 = fminf(mA1, __shfl_xor_sync(0xFFFFFFFFu, mA1, 2));
            mB1 = fminf(mB1, __shfl_xor_sync(0xFFFFFFFFu, mB1, 1));
            mB1 = fminf(mB1, __shfl_xor_sync(0xFFFFFFFFu, mB1, 2));
            if (q == 0) {
                float* ob = out + (size_t)b * (OH * OW);
                int r0 = oh0 + wid * 2, r1 = r0 + 1;
                int cA = ow0 + (lane >> 2), cB = cA + 8;
                bool okA = cA < OW, okB = cB < OW;
                if (r0 < OH) {
                    if (okA) ob[r0 * OW + cA] = tanhf(tanhf(mA0));
                    if (okB) ob[r0 * OW + cB] = tanhf(tanhf(mB0));
                }
                if (r1 < OH) {
                    if (okA) ob[r1 * OW + cA] = tanhf(tanhf(mA1));
                    if (okB) ob[r1 * OW + cB] = tanhf(tanhf(mB1));
                }
            }
        }

        __syncthreads();   // halo[t+1] stores visible; GEMM t reads complete
    }
}

// ============ launch ============
extern "C" void kernel_launch(void* const* d_in, const int* in_sizes, int n_in,
                              void* d_out, int out_size)
{
    const float* x    = (const float*)d_in[0];
    const float* wg   = (const float*)d_in[1];
    const float* bias = (const float*)d_in[2];
    float* out = (float*)d_out;

    cudaFuncSetAttribute(conv_mma_kernel,
                         cudaFuncAttributeMaxDynamicSharedMemorySize, SMEM_BYTES);

    wprep_kernel<<<(NCHUNK * 8 * 32 + 255) / 256, 256>>>(wg);

    dim3 grid((OW + PT * TPC - 1) / (PT * TPC),   // 4
              (OH + PT - 1) / PT,                 // 16
              B_);                                // 64
    conv_mma_kernel<<<grid, THREADS, SMEM_BYTES>>>(x, bias, out);
}

// round 17
// speedup vs baseline: 1.3981x; 1.3981x over previous
#include <cuda_runtime.h>
#include <cuda_fp16.h>
#include <math.h>

typedef unsigned int u32;

// ---- problem constants ----
#define B_    64
#define CIN   16
#define H_    256
#define W_    256
#define COUT  64
#define OH    254
#define OW    254

// ---- implicit GEMM tiling: 128 pixels (8x16) x 64 co, K = 144 = 9 x 16 ----
#define PT_H    8
#define PT_W    16
#define KTOT    144
#define NCHUNK  9
#define THREADS 256
#define TPC     8            // tiles per CTA (along width)

// ---- smem layout (bytes) ----
#define OFF_BIASP 0                          // float2[32] bias pairs (256 B)
#define OFF_LUT   256                        // u32[72] packed u16 offset pairs (288 B)
#define OFF_HALO0 1024                       // fp32 [16][10][20] = 12800 B
#define OFF_HALO1 (OFF_HALO0 + 12800)
#define OFF_BF    (OFF_HALO1 + 12800)        // B fragments, 80 B/lane pitch = 23040 B
#define SMEM_BYTES (OFF_BF + 23040)          // 49664  (x4 CTAs = 198656 <= 227KB)

// B fragments: u32[(c*32+lane)*20 + nb*2 + r]  (lane pitch 20 u32 = 80 B, 64 used)
__device__ u32 g_Bf[NCHUNK * 32 * 20];

// m16n8k16 row.col f32.f16.f16.f32
__device__ __forceinline__ void mma16816(float c[4], const u32 a[4], u32 b0, u32 b1) {
    asm volatile(
        "mma.sync.aligned.m16n8k16.row.col.f32.f16.f16.f32 "
        "{%0,%1,%2,%3}, {%4,%5,%6,%7}, {%8,%9}, {%0,%1,%2,%3};"
        : "+f"(c[0]), "+f"(c[1]), "+f"(c[2]), "+f"(c[3])
        : "r"(a[0]), "r"(a[1]), "r"(a[2]), "r"(a[3]), "r"(b0), "r"(b1));
}
__device__ __forceinline__ u32 pkhf2(float hi_f, float lo_f) {
    u32 r; asm("cvt.rn.f16x2.f32 %0, %1, %2;" : "=r"(r) : "f"(hi_f), "f"(lo_f)); return r;
}

// ============ weight prep: fp16 fragment-layout into g_Bf (padded pitch) ============
__global__ void wprep_kernel(const float* __restrict__ wg) {
    int idx = blockIdx.x * blockDim.x + threadIdx.x;      // (c, nb, lane)
    if (idx >= NCHUNK * 8 * 32) return;
    int lane = idx & 31;
    int nb   = (idx >> 5) & 7;
    int c    = idx >> 8;                                  // 0..8
    int n = nb * 8 + (lane >> 2);
    #pragma unroll
    for (int r = 0; r < 2; r++) {
        int kbase = c * 16 + r * 8 + 2 * (lane & 3);
        u32 pack = 0;
        #pragma unroll
        for (int e = 0; e < 2; e++) {
            int k = kbase + e;
            float v = 0.0f;
            if (k < KTOT) {
                int ci = k / 9, r9 = k % 9, kh = r9 / 3, kw = r9 % 3;
                v = wg[((n * CIN + ci) * 3 + kh) * 3 + kw];
            }
            pack |= (u32)__half_as_ushort(__float2half_rn(v)) << (e * 16);
        }
        g_Bf[(c * 32 + lane) * 20 + nb * 2 + r] = pack;
    }
}

// ============ main kernel ============
__global__ __launch_bounds__(THREADS, 4)
void conv_mma_kernel(const float* __restrict__ x,
                     const float* __restrict__ bias,
                     float* __restrict__ out)
{
    extern __shared__ __align__(16) unsigned char smem[];
    const int tid  = threadIdx.x;
    const int wid  = tid >> 5;
    const int lane = tid & 31;
    const int q    = lane & 3;
    const int b    = blockIdx.z;
    const int oh0  = blockIdx.y * PT_H;
    const int owg  = blockIdx.x * (PT_W * TPC);
    const float* xb = x + (size_t)b * (CIN * H_ * W_);

    // ---- one-time per CTA: B fragments, bias pairs, packed offset LUT, halo[0] ----
    {
        uint4*       d = (uint4*)(smem + OFF_BF);
        const uint4* s = (const uint4*)g_Bf;
        #pragma unroll 1
        for (int i = tid; i < 23040 / 16; i += THREADS) d[i] = s[i];
    }
    if (tid < 32) {
        int nb = tid >> 2, j = tid & 3;
        ((float2*)(smem + OFF_BIASP))[tid] =
            make_float2(bias[nb * 8 + 2 * j], bias[nb * 8 + 2 * j + 1]);
    }
    if (tid < 72) {   // packed offsets: idx = c*8 + q*2 + half; k0 = c*16 + 2q + 8*half
        int half = tid & 1, qq = (tid >> 1) & 3, c = tid >> 3;
        int k0 = c * 16 + 2 * qq + 8 * half;
        u32 o0, o1;
        {
            int k = k0, ci = k / 9, r9 = k % 9, kh = r9 / 3, kw = r9 % 3;
            o0 = (u32)(((ci * 10 + kh) * 20 + kw) * 4);
        }
        {
            int k = k0 + 1, ci = k / 9, r9 = k % 9, kh = r9 / 3, kw = r9 % 3;
            o1 = (u32)(((ci * 10 + kh) * 20 + kw) * 4);
        }
        ((u32*)(smem + OFF_LUT))[tid] = o0 | (o1 << 16);
    }
    // halo for tile 0 into buffer 0
    {
        float* halo = (float*)(smem + OFF_HALO0);
        const int ow0 = owg;
        #pragma unroll 1
        for (int i = tid; i < CIN * 10 * 18; i += THREADS) {
            int ci = i / 180; int rem = i - ci * 180;
            int r = rem / 18; int c = rem - r * 18;
            int gr = oh0 + r, gc = ow0 + c;
            float v = 0.0f;
            if (gr < H_ && gc < W_) v = xb[ci * (H_ * W_) + gr * W_ + gc];
            halo[(ci * 10 + r) * 20 + c] = v;
        }
    }
    __syncthreads();

    // per-thread invariants (LUT stays in smem to fit the 64-reg budget)
    const uint2* lutp = (const uint2*)(smem + OFF_LUT);   // [c*4 + q] -> (pk0, pk1)
    const unsigned char* bfp = smem + OFF_BF + lane * 80;
    const u32 haloOffA = (u32)((wid * 20 + (lane >> 2)) * 4);   // pixel (row=wid, col=lane>>2)

    #pragma unroll 1
    for (int t = 0; t < TPC; t++) {
        const int ow0 = owg + t * PT_W;
        const unsigned char* haloA  = smem + ((t & 1) ? OFF_HALO1 : OFF_HALO0) + haloOffA;
        const unsigned char* haloB8 = haloA + 32;               // +8 pixel cols

        // ---- per-warp GEMM: 16 pixels x 64 co, A frags built in regs (fp16) ----
        float acc[8][4];
        #pragma unroll
        for (int nb = 0; nb < 8; nb++)
            #pragma unroll
            for (int r = 0; r < 4; r++) acc[nb][r] = 0.0f;

        #pragma unroll
        for (int c = 0; c < NCHUNK; c++) {
            uint2 pk = lutp[c * 4 + q];       // broadcast LDS.64
            u32 oA = pk.x & 0xFFFFu, oB = pk.x >> 16;
            u32 oC = pk.y & 0xFFFFu, oD = pk.y >> 16;
            float vA0 = *(const float*)(haloA  + oA);
            float vA1 = *(const float*)(haloA  + oB);
            float vA8 = *(const float*)(haloA  + oC);
            float vA9 = *(const float*)(haloA  + oD);
            float vB0 = *(const float*)(haloB8 + oA);
            float vB1 = *(const float*)(haloB8 + oB);
            float vB8 = *(const float*)(haloB8 + oC);
            float vB9 = *(const float*)(haloB8 + oD);

            u32 ah[4];
            ah[0] = pkhf2(vA1, vA0);
            ah[1] = pkhf2(vB1, vB0);
            ah[2] = pkhf2(vA9, vA8);
            ah[3] = pkhf2(vB9, vB8);

            const uint4* bq = (const uint4*)(bfp + c * 2560);
            uint4 w01 = bq[0];
            uint4 w23 = bq[1];
            mma16816(acc[0], ah, w01.x, w01.y);
            mma16816(acc[1], ah, w01.z, w01.w);
            mma16816(acc[2], ah, w23.x, w23.y);
            mma16816(acc[3], ah, w23.z, w23.w);
            uint4 w45 = bq[2];
            uint4 w67 = bq[3];
            mma16816(acc[4], ah, w45.x, w45.y);
            mma16816(acc[5], ah, w45.z, w45.w);
            mma16816(acc[6], ah, w67.x, w67.y);
            mma16816(acc[7], ah, w67.z, w67.w);
        }

        // ---- prefetch halo for tile t+1 into the other buffer (overlaps epilogue) ----
        if (t + 1 < TPC) {
            float* halo = (float*)(smem + ((t & 1) ? OFF_HALO0 : OFF_HALO1));
            const int ow1 = ow0 + PT_W;
            #pragma unroll 1
            for (int i = tid; i < CIN * 10 * 18; i += THREADS) {
                int ci = i / 180; int rem = i - ci * 180;
                int r = rem / 18; int c = rem - r * 18;
                int gr = oh0 + r, gc = ow1 + c;
                float v = 0.0f;
                if (gr < H_ && gc < W_) v = xb[ci * (H_ * W_) + gr * W_ + gc];
                halo[(ci * 10 + r) * 20 + c] = v;
            }
        }

        // ---- epilogue: +bias, min over co, tanh^2, store ----
        {
            const float2* bp = (const float2*)(smem + OFF_BIASP);
            float mA = INFINITY, mB = INFINITY;
            #pragma unroll
            for (int nb = 0; nb < 8; nb++) {
                float2 bb = bp[nb * 4 + q];
                mA = fminf(mA, fminf(acc[nb][0] + bb.x, acc[nb][1] + bb.y));
                mB = fminf(mB, fminf(acc[nb][2] + bb.x, acc[nb][3] + bb.y));
            }
            mA = fminf(mA, __shfl_xor_sync(0xFFFFFFFFu, mA, 1));
            mA = fminf(mA, __shfl_xor_sync(0xFFFFFFFFu, mA, 2));
            mB = fminf(mB, __shfl_xor_sync(0xFFFFFFFFu, mB, 1));
            mB = fminf(mB, __shfl_xor_sync(0xFFFFFFFFu, mB, 2));
            // all quad lanes hold both mins: q=0 evaluates mA, q=1 evaluates mB
            float y = tanhf(tanhf((q & 1) ? mB : mA));
            if (q < 2) {
                float* ob = out + (size_t)b * (OH * OW);
                int row = oh0 + wid;
                int col = ow0 + (lane >> 2) + ((q & 1) << 3);
                if (row < OH && col < OW) ob[row * OW + col] = y;
            }
        }

        __syncthreads();   // halo[t+1] stores visible; GEMM t reads complete
    }
}

// ============ launch ============
extern "C" void kernel_launch(void* const* d_in, const int* in_sizes, int n_in,
                              void* d_out, int out_size)
{
    const float* x    = (const float*)d_in[0];
    const float* wg   = (const float*)d_in[1];
    const float* bias = (const float*)d_in[2];
    float* out = (float*)d_out;

    cudaFuncSetAttribute(conv_mma_kernel,
                         cudaFuncAttributeMaxDynamicSharedMemorySize, SMEM_BYTES);

    wprep_kernel<<<(NCHUNK * 8 * 32 + 255) / 256, 256>>>(wg);

    dim3 grid((OW + PT_W * TPC - 1) / (PT_W * TPC),   // 2
              (OH + PT_H - 1) / PT_H,                 // 32
              B_);                                    // 64
    conv_mma_kernel<<<grid, THREADS, SMEM_BYTES>>>(x, bias, out);
}